// round 6
// baseline (speedup 1.0000x reference)
#include <cuda_runtime.h>

#define IN_DIM   2048
#define OUT_DIM  14951
#define THREADS  256
#define ROWS_PER_CTA 4
#define EPS      1e-12f

__global__ __launch_bounds__(THREADS)
void hc_kernel(const float* __restrict__ x,
               const float* __restrict__ scale,
               const float* __restrict__ bias,
               float* __restrict__ out)
{
    __shared__ float xch[8][THREADS];      // 8 KB exchange buffer (conflict-free)
    __shared__ float sred[THREADS / 32];
    __shared__ float sc;

    const int t    = threadIdx.x;
    const int lane = t & 31;
    const float scl = scale[0];

    // ---- sequential loop over 4 rows: res[8] fully reused, regs stay ~R3 ----
#pragma unroll 1
    for (int r = 0; r < ROWS_PER_CTA; ++r) {
        const int row = blockIdx.x * ROWS_PER_CTA + r;

        float res[8];   // res[q] = element n = q*256 + t of this row
        const float* __restrict__ xr = x + (size_t)row * IN_DIM;

        // ---- load (coalesced) + sum of squares ----
        float ss = 0.f;
#pragma unroll
        for (int q = 0; q < 8; ++q) {
            float v = xr[q * THREADS + t];
            res[q] = v;
            ss += v * v;
        }
#pragma unroll
        for (int o = 16; o; o >>= 1) ss += __shfl_xor_sync(0xFFFFFFFFu, ss, o);
        if (lane == 0) sred[t >> 5] = ss;
        __syncthreads();                        // also protects sc/xch from prev row
        if (t == 0) {
            float tot = 0.f;
#pragma unroll
            for (int w = 0; w < THREADS / 32; ++w) tot += sred[w];
            sc = -scl * rsqrtf(fmaxf(tot, EPS));
        }

        // ---- 3 register stages (bits 8..10 of n == bits of q) ----
#pragma unroll
        for (int B = 1; B < 8; B <<= 1) {
#pragma unroll
            for (int q = 0; q < 8; ++q) {
                if (!(q & B)) {
                    float a0 = res[q], a1 = res[q | B];
                    res[q]     = a0 + a1;
                    res[q | B] = a0 - a1;
                }
            }
        }

        // ---- 5 shuffle stages (bits 0..4 of n == lane bits of t) ----
#pragma unroll
        for (int h = 1; h <= 16; h <<= 1) {
#pragma unroll
            for (int q = 0; q < 8; ++q) {
                float o = __shfl_xor_sync(0xFFFFFFFFu, res[q], h);
                res[q] = (t & h) ? (o - res[q]) : (res[q] + o);
            }
        }

        // ---- 3 smem exchange stages (bits 5..7 of n == warp bits of t) ----
#pragma unroll
        for (int h = 32; h <= 128; h <<= 1) {
            __syncthreads();
#pragma unroll
            for (int q = 0; q < 8; ++q) xch[q][t] = res[q];
            __syncthreads();
#pragma unroll
            for (int q = 0; q < 8; ++q) {
                float o = xch[q][t ^ h];
                res[q] = (t & h) ? (o - res[q]) : (res[q] + o);
            }
        }

        __syncthreads();
        const float c = sc;
        float* __restrict__ orow = out + (size_t)row * OUT_DIM;

        // ---- epilogue (R3 structure: fully unrolled, register-resident y) ----
        // out[row, j] = c * y[j & 2047] + bias[j];  j = t + 256*m => y = res[m & 7]
#pragma unroll
        for (int m0 = 0; m0 < 56; m0 += 8) {          // 7 full 2048-chunks
#pragma unroll
            for (int u = 0; u < 8; ++u) {
                int j = t + ((m0 + u) << 8);
                orow[j] = fmaf(c, res[u], __ldg(bias + j));
            }
        }
#pragma unroll
        for (int u = 0; u < 8; ++u) {                 // tail chunk (j < 14951)
            int j = t + ((56 + u) << 8);
            if (j < OUT_DIM) orow[j] = fmaf(c, res[u], __ldg(bias + j));
        }
    }
}

extern "C" void kernel_launch(void* const* d_in, const int* in_sizes, int n_in,
                              void* d_out, int out_size)
{
    const float* x     = (const float*)d_in[0];
    const float* scale = (const float*)d_in[1];
    const float* bias  = (const float*)d_in[2];
    float* out = (float*)d_out;

    const int batch = in_sizes[0] / IN_DIM;             // 4096
    hc_kernel<<<batch / ROWS_PER_CTA, THREADS>>>(x, scale, bias, out);
}

// round 7
// speedup vs baseline: 1.5910x; 1.5910x over previous
#include <cuda_runtime.h>

#define IN_DIM   2048
#define OUT_DIM  14951
#define THREADS  256
#define EPS      1e-12f

__global__ __launch_bounds__(THREADS, 8)
void hc_kernel(const float* __restrict__ x,
               const float* __restrict__ scale,
               const float* __restrict__ bias,
               float* __restrict__ out)
{
    __shared__ float xch[8][THREADS];      // 8 KB exchange buffer (conflict-free)
    __shared__ float sred[THREADS / 32];
    __shared__ float sc;

    const int t    = threadIdx.x;
    const int row  = blockIdx.x;
    const int lane = t & 31;

    // res[q] holds element n = q*256 + t of this row's transform
    float res[8];

    const float* __restrict__ xr = x + (size_t)row * IN_DIM;

    // ---- load (coalesced) + sum of squares ----
    float ss = 0.f;
#pragma unroll
    for (int q = 0; q < 8; ++q) {
        float v = xr[q * THREADS + t];
        res[q] = v;
        ss += v * v;
    }
#pragma unroll
    for (int o = 16; o; o >>= 1) ss += __shfl_xor_sync(0xFFFFFFFFu, ss, o);
    if (lane == 0) sred[t >> 5] = ss;
    __syncthreads();
    if (t == 0) {
        float tot = 0.f;
#pragma unroll
        for (int w = 0; w < THREADS / 32; ++w) tot += sred[w];
        sc = -scale[0] * rsqrtf(fmaxf(tot, EPS));
    }

    // ---- 3 register stages (bits 8..10 of n == bits of q) ----
#pragma unroll
    for (int B = 1; B < 8; B <<= 1) {
#pragma unroll
        for (int q = 0; q < 8; ++q) {
            if (!(q & B)) {
                float a0 = res[q], a1 = res[q | B];
                res[q]     = a0 + a1;
                res[q | B] = a0 - a1;
            }
        }
    }

    // ---- 5 shuffle stages (bits 0..4 of n == lane bits of t) ----
#pragma unroll
    for (int h = 1; h <= 16; h <<= 1) {
#pragma unroll
        for (int q = 0; q < 8; ++q) {
            float o = __shfl_xor_sync(0xFFFFFFFFu, res[q], h);
            res[q] = (t & h) ? (o - res[q]) : (res[q] + o);
        }
    }

    // ---- 3 smem exchange stages (bits 5..7 of n == warp bits of t) ----
#pragma unroll
    for (int h = 32; h <= 128; h <<= 1) {
        __syncthreads();
#pragma unroll
        for (int q = 0; q < 8; ++q) xch[q][t] = res[q];
        __syncthreads();
#pragma unroll
        for (int q = 0; q < 8; ++q) {
            float o = xch[q][t ^ h];
            res[q] = (t & h) ? (o - res[q]) : (res[q] + o);
        }
    }

    __syncthreads();
    const float c = sc;
    float* __restrict__ orow = out + (size_t)row * OUT_DIM;

    // ---- epilogue: out[row, j] = c * y[j & 2047] + bias[j]
    // j = t + 256*m  =>  y[j & 2047] = res[m & 7]   (register-resident)
    //
    // Tail chunk (m0=56, predicated) first, then the 7 full chunks in an order
    // ROTATED by blockIdx so concurrent CTAs don't read the same bias lines in
    // lockstep (decorrelates LTS-slice contention). Streaming stores (cs) keep
    // the 245MB write stream from thrashing L2.
#pragma unroll
    for (int u = 0; u < 8; ++u) {
        int j = t + ((56 + u) << 8);
        if (j < OUT_DIM) __stcs(orow + j, fmaf(c, res[u], __ldg(bias + j)));
    }

    const int cbase = row % 7;
#pragma unroll
    for (int cc = 0; cc < 7; ++cc) {
        int chunk = cbase + cc;
        if (chunk >= 7) chunk -= 7;            // (cbase+cc) mod 7, no IMUL
        const int m0 = chunk << 3;
#pragma unroll
        for (int u = 0; u < 8; ++u) {
            int j = t + ((m0 + u) << 8);
            __stcs(orow + j, fmaf(c, res[u], __ldg(bias + j)));
        }
    }
}

extern "C" void kernel_launch(void* const* d_in, const int* in_sizes, int n_in,
                              void* d_out, int out_size)
{
    const float* x     = (const float*)d_in[0];
    const float* scale = (const float*)d_in[1];
    const float* bias  = (const float*)d_in[2];
    float* out = (float*)d_out;

    const int batch = in_sizes[0] / IN_DIM;     // 4096
    hc_kernel<<<batch, THREADS>>>(x, scale, bias, out);
}